// round 1
// baseline (speedup 1.0000x reference)
#include <cuda_runtime.h>
#include <math.h>

// ---------------------------------------------------------------------------
// NCA_3D: y = x + MLP(perc(x)) * floor(mask+0.25);  out = y * (maxpool3(y[:,3]) > 0.1)
// B=8, C=16, S=64, HID=32.  All fp32.
// Pass 1: fused Sobel + 64->32->16 MLP, weights in __constant__ (LDCU path).
// Pass 2: alpha 3x3x3 maxpool (edge-clamped, -inf pad); only dead voxels stored.
// ---------------------------------------------------------------------------

__constant__ float cW1[32 * 64];
__constant__ float cb1[32];
__constant__ float cW2[16 * 32];

// scratch: alpha plane (B=8 x 64^3)
__device__ float g_alpha[8u << 18];

#define S_CH 600           // per-channel halo slab: 6*10*10
#define TILE_THREADS 256

__global__ __launch_bounds__(TILE_THREADS, 2)
void nca_pass1(const float* __restrict__ x, const float* __restrict__ rmask,
               float* __restrict__ out)
{
    __shared__ float sm[16 * S_CH];   // 38400 B

    int blk = blockIdx.x;
    int w0 = (blk & 7) << 3;
    int h0 = ((blk >> 3) & 7) << 3;
    int d0 = ((blk >> 6) & 15) << 2;
    int b  = blk >> 10;
    const size_t baseB = (size_t)b << 22;   // b * 16 * 64^3

    int tid = threadIdx.x;

    // ---- stage x tile (wrap halo) ----
    for (int i = tid; i < 16 * S_CH; i += TILE_THREADS) {
        int c = i / S_CH;
        int r = i - c * S_CH;
        int dd = r / 100; r -= dd * 100;
        int hh = r / 10;
        int ww = r - hh * 10;
        int gd = (d0 + dd - 1) & 63;
        int gh = (h0 + hh - 1) & 63;
        int gw = (w0 + ww - 1) & 63;
        sm[i] = x[baseB + ((size_t)c << 18) + ((size_t)gd << 12) + (gh << 6) + gw];
    }
    __syncthreads();

    int wx = tid & 7, hy = (tid >> 3) & 7, dz = tid >> 6;

    float h[32];
#pragma unroll
    for (int o = 0; o < 32; o++) h[o] = cb1[o];

#pragma unroll 1
    for (int c = 0; c < 16; c++) {
        const float* s = sm + c * S_CH + dz * 100 + hy * 10 + wx;
        float v[27];
#pragma unroll
        for (int i = 0; i < 3; i++)
#pragma unroll
            for (int j = 0; j < 3; j++)
#pragma unroll
                for (int k = 0; k < 3; k++)
                    v[(i * 3 + j) * 3 + k] = s[i * 100 + j * 10 + k];

        // a[j][k] = sum_i H[i] v[i][j][k],  H = (1,2,1)
        float a[9];
#pragma unroll
        for (int j = 0; j < 3; j++)
#pragma unroll
            for (int k = 0; k < 3; k++)
                a[j * 3 + k] = fmaf(2.f, v[9 + j * 3 + k], v[j * 3 + k] + v[18 + j * 3 + k]);

        // gx = sum_j H[j] (a[j][2] - a[j][0])
        float gx = fmaf(2.f, a[3 + 2] - a[3 + 0],
                        (a[0 + 2] - a[0 + 0]) + (a[6 + 2] - a[6 + 0]));
        // gy = sum_k H[k] (a[2][k] - a[0][k])
        float gy = fmaf(2.f, a[6 + 1] - a[0 + 1],
                        (a[6 + 0] - a[0 + 0]) + (a[6 + 2] - a[0 + 2]));
        // gz = sum_{j,k} H[j]H[k] (v[2][j][k] - v[0][j][k])
        float r0 = fmaf(2.f, v[18 + 1] - v[1],  (v[18 + 0] - v[0]) + (v[18 + 2] - v[2]));
        float r1 = fmaf(2.f, v[21 + 1] - v[4],  (v[21 + 0] - v[3]) + (v[21 + 2] - v[5]));
        float r2 = fmaf(2.f, v[24 + 1] - v[7],  (v[24 + 0] - v[6]) + (v[24 + 2] - v[8]));
        float gz = fmaf(2.f, r1, r0 + r2);

        float xc = v[13];

#pragma unroll
        for (int o = 0; o < 32; o++) {
            float t = fmaf(cW1[o * 64 + c],      gx, h[o]);
            t       = fmaf(cW1[o * 64 + 16 + c], gy, t);
            t       = fmaf(cW1[o * 64 + 32 + c], gz, t);
            h[o]    = fmaf(cW1[o * 64 + 48 + c], xc, t);
        }
    }

#pragma unroll
    for (int o = 0; o < 32; o++) h[o] = fmaxf(h[o], 0.f);

    int d = d0 + dz, hh2 = h0 + hy, ww2 = w0 + wx;
    size_t sp = ((size_t)d << 12) + (hh2 << 6) + ww2;

#pragma unroll 1
    for (int c2 = 0; c2 < 16; c2++) {
        float dy = 0.f;
#pragma unroll
        for (int o = 0; o < 32; o++) dy = fmaf(cW2[c2 * 32 + o], h[o], dy);
        float xv = sm[c2 * S_CH + (dz + 1) * 100 + (hy + 1) * 10 + (wx + 1)];
        size_t gi = baseB + ((size_t)c2 << 18) + sp;
        float u  = floorf(rmask[gi] + 0.25f);
        float yv = fmaf(dy, u, xv);
        out[gi] = yv;
        if (c2 == 3) g_alpha[((size_t)b << 18) + sp] = yv;
    }
}

__global__ __launch_bounds__(TILE_THREADS)
void nca_pass2(float* __restrict__ out)
{
    __shared__ float sa[S_CH];

    int blk = blockIdx.x;
    int w0 = (blk & 7) << 3;
    int h0 = ((blk >> 3) & 7) << 3;
    int d0 = ((blk >> 6) & 15) << 2;
    int b  = blk >> 10;
    int tid = threadIdx.x;

    const float* ap = g_alpha + ((size_t)b << 18);
    for (int i = tid; i < S_CH; i += TILE_THREADS) {
        int dd = i / 100; int r = i - dd * 100;
        int hh = r / 10;  int ww = r - hh * 10;
        int gd = d0 + dd - 1, gh = h0 + hh - 1, gw = w0 + ww - 1;
        float val = -3.4e38f;
        if ((unsigned)gd < 64u && (unsigned)gh < 64u && (unsigned)gw < 64u)
            val = ap[((size_t)gd << 12) + (gh << 6) + gw];
        sa[i] = val;
    }
    __syncthreads();

    int wx = tid & 7, hy = (tid >> 3) & 7, dz = tid >> 6;
    const float* s = sa + dz * 100 + hy * 10 + wx;
    float m = -3.4e38f;
#pragma unroll
    for (int i = 0; i < 3; i++)
#pragma unroll
        for (int j = 0; j < 3; j++)
#pragma unroll
            for (int k = 0; k < 3; k++)
                m = fmaxf(m, s[i * 100 + j * 10 + k]);

    if (!(m > 0.1f)) {
        // dead voxel (vanishingly rare): zero all channels
        size_t sp = ((size_t)b << 22) + ((size_t)(d0 + dz) << 12) + ((h0 + hy) << 6) + (w0 + wx);
#pragma unroll
        for (int c = 0; c < 16; c++)
            out[sp + ((size_t)c << 18)] = 0.f;
    }
}

extern "C" void kernel_launch(void* const* d_in, const int* in_sizes, int n_in,
                              void* d_out, int out_size)
{
    const float* x   = (const float*)d_in[0];
    const float* rm  = (const float*)d_in[1];
    const float* W1  = (const float*)d_in[2];
    const float* b1  = (const float*)d_in[3];
    const float* W2  = (const float*)d_in[4];
    float* out = (float*)d_out;

    int B = in_sizes[0] >> 22;   // elements / (16*64^3)

    cudaMemcpyToSymbolAsync(cW1, W1, 32 * 64 * sizeof(float), 0, cudaMemcpyDeviceToDevice, 0);
    cudaMemcpyToSymbolAsync(cb1, b1, 32 * sizeof(float),       0, cudaMemcpyDeviceToDevice, 0);
    cudaMemcpyToSymbolAsync(cW2, W2, 16 * 32 * sizeof(float),  0, cudaMemcpyDeviceToDevice, 0);

    int blocks = B << 10;   // B * 16(d) * 8(h) * 8(w)
    nca_pass1<<<blocks, TILE_THREADS>>>(x, rm, out);
    nca_pass2<<<blocks, TILE_THREADS>>>(out);
}